// round 11
// baseline (speedup 1.0000x reference)
#include <cuda_runtime.h>
#include <math.h>

// Lin2d: x <- x @ Mt, 1000 times, Mt = [[c,-s],[s,c]] (float32 c,s).
// Collapsed to one complex multiply by w = (c - i*s)^1000 (host double math).
// Persistent single-wave grid-stride kernel: exactly one resident wave
// (148 SMs x 8 blocks), unroll-4 independent LDG.128 per iteration (MLP=4),
// evict-first cache hints since each byte is touched exactly once.

#define NBLOCKS 1184   // 148 SMs * 8 resident CTAs (256 thr, ~32 regs)

__device__ __forceinline__ float4 rot4(float4 v, float wr, float wi) {
    float4 r;
    r.x = fmaf(wr, v.x, -wi * v.y);
    r.y = fmaf(wi, v.x,  wr * v.y);
    r.z = fmaf(wr, v.z, -wi * v.w);
    r.w = fmaf(wi, v.z,  wr * v.w);
    return r;
}

__global__ void __launch_bounds__(256, 8)
lin2d_apply_kernel(const float4* __restrict__ in,
                   float4* __restrict__ out,
                   int n4, float wr, float wi) {
    const int stride = gridDim.x * blockDim.x;
    int i = blockIdx.x * blockDim.x + threadIdx.x;

    // Main loop: 4 independent, front-batched 128-bit loads per iteration.
    for (; i + 3 * stride < n4; i += 4 * stride) {
        float4 v0 = __ldcs(in + i);
        float4 v1 = __ldcs(in + i + stride);
        float4 v2 = __ldcs(in + i + 2 * stride);
        float4 v3 = __ldcs(in + i + 3 * stride);
        __stcs(out + i,              rot4(v0, wr, wi));
        __stcs(out + i + stride,     rot4(v1, wr, wi));
        __stcs(out + i + 2 * stride, rot4(v2, wr, wi));
        __stcs(out + i + 3 * stride, rot4(v3, wr, wi));
    }
    // Remainder.
    for (; i < n4; i += stride) {
        float4 v = __ldcs(in + i);
        __stcs(out + i, rot4(v, wr, wi));
    }
}

extern "C" void kernel_launch(void* const* d_in, const int* in_sizes, int n_in,
                              void* d_out, int out_size) {
    const float* x = (const float*)d_in[0];
    float* y = (float*)d_out;
    const int n = in_sizes[0];       // total floats = BATCH*2 (multiple of 4)
    const int n4 = n / 4;

    // Host-side constants (pure math at capture time; deterministic).
    const double theta = 3.14159265358979323846 / 100.0;
    const double c = (double)((float)cos(theta));
    const double s = (double)((float)sin(theta));
    const int N = 1000;
    const double r   = hypot(c, s);
    const double phi = atan2(s, c);
    const double mag = pow(r, (double)N);
    // w = (c - i*s)^N = mag * (cos(N*phi) - i*sin(N*phi))
    const float wr = (float)(mag * cos((double)N * phi));
    const float wi = (float)(-mag * sin((double)N * phi));

    const int threads = 256;
    int blocks = (n4 + threads - 1) / threads;
    if (blocks > NBLOCKS) blocks = NBLOCKS;
    lin2d_apply_kernel<<<blocks, threads>>>((const float4*)x, (float4*)y,
                                            n4, wr, wi);
}

// round 13
// speedup vs baseline: 1.1463x; 1.1463x over previous
#include <cuda_runtime.h>
#include <math.h>

// Lin2d: x <- x @ Mt, 1000 times, Mt = [[c,-s],[s,c]] (float32 c,s).
// Collapsed to one complex multiply by w = (c - i*s)^1000 (host double math).
// Flat tiled streaming kernel (best layout per R11 post-mortem): each CTA
// covers a contiguous tile, 2 independent float4s per thread (MLP=2),
// evict-first cache hints since each byte is touched exactly once.

__device__ __forceinline__ float4 rot4(float4 v, float wr, float wi) {
    float4 r;
    r.x = fmaf(wr, v.x, -wi * v.y);
    r.y = fmaf(wi, v.x,  wr * v.y);
    r.z = fmaf(wr, v.z, -wi * v.w);
    r.w = fmaf(wi, v.z,  wr * v.w);
    return r;
}

__global__ void __launch_bounds__(512)
lin2d_apply_kernel(const float4* __restrict__ in,
                   float4* __restrict__ out,
                   int n4, float wr, float wi) {
    const int bd = blockDim.x;
    int base = blockIdx.x * (bd * 2) + threadIdx.x;
    int i1 = base + bd;

    if (i1 < n4) {
        // Fast path: full tile (all blocks when n4 % (2*bd) == 0).
        float4 v0 = __ldcs(in + base);
        float4 v1 = __ldcs(in + i1);
        __stcs(out + base, rot4(v0, wr, wi));
        __stcs(out + i1,   rot4(v1, wr, wi));
    } else if (base < n4) {
        float4 v0 = __ldcs(in + base);
        __stcs(out + base, rot4(v0, wr, wi));
    }
}

extern "C" void kernel_launch(void* const* d_in, const int* in_sizes, int n_in,
                              void* d_out, int out_size) {
    const float* x = (const float*)d_in[0];
    float* y = (float*)d_out;
    const int n = in_sizes[0];       // total floats = BATCH*2 (multiple of 4)
    const int n4 = n / 4;

    // Host-side constants (pure math at capture time; deterministic).
    const double theta = 3.14159265358979323846 / 100.0;
    const double c = (double)((float)cos(theta));
    const double s = (double)((float)sin(theta));
    const int N = 1000;
    const double r   = hypot(c, s);
    const double phi = atan2(s, c);
    const double mag = pow(r, (double)N);
    // w = (c - i*s)^N = mag * (cos(N*phi) - i*sin(N*phi))
    const float wr = (float)(mag * cos((double)N * phi));
    const float wi = (float)(-mag * sin((double)N * phi));

    const int threads = 512;
    const int per_block = threads * 2;
    const int blocks = (n4 + per_block - 1) / per_block;
    lin2d_apply_kernel<<<blocks, threads>>>((const float4*)x, (float4*)y,
                                            n4, wr, wi);
}